// round 1
// baseline (speedup 1.0000x reference)
#include <cuda_runtime.h>

// Problem shape (fixed by the dataset): source [B,N,3], target [B,M,3], fp32.
#define Bq 2
#define Nq 8192
#define Mq 8192
#define THREADS 256
#define S_PT 4                                  // sources per thread (register blocked)
#define SRC_PER_BLOCK (THREADS * S_PT)          // 1024
#define NCHUNK 32                               // target chunks -> grid parallelism
#define CHUNK (Mq / NCHUNK)                     // 256 targets per chunk (== THREADS)
#define SRCBLK_PER_B (Nq / SRC_PER_BLOCK)       // 8
#define NSRCBLK (Bq * SRCBLK_PER_B)             // 16
#define BN (Bq * Nq)                            // 16384 sources total
#define NRBLK (BN / THREADS)                    // 64 reduce blocks

// Scratch (no allocations allowed): target SoA + half-norms, per-chunk partial mins,
// per-block partial sums.
__device__ float g_tsoa[Bq * 4 * Mq];           // [b][{x,y,z,ht2}][M]
__device__ float g_partial[NCHUNK * BN];        // [chunk][global source]
__device__ float g_blocksum[NRBLK];

// ---- packed f32x2 helpers (sm_100+; ptxas will not auto-fuse, must be PTX) ----
__device__ __forceinline__ unsigned long long pack2(float a, float b) {
    unsigned long long r;
    asm("mov.b64 %0, {%1, %2};" : "=l"(r) : "f"(a), "f"(b));
    return r;
}
__device__ __forceinline__ unsigned long long fma2(unsigned long long a,
                                                   unsigned long long b,
                                                   unsigned long long c) {
    unsigned long long d;
    asm("fma.rn.f32x2 %0, %1, %2, %3;" : "=l"(d) : "l"(a), "l"(b), "l"(c));
    return d;
}
__device__ __forceinline__ float lo2(unsigned long long v) {
    return __uint_as_float((unsigned int)v);
}
__device__ __forceinline__ float hi2(unsigned long long v) {
    return __uint_as_float((unsigned int)(v >> 32));
}

// Kernel 1: transpose targets to SoA and precompute ht2 = 0.5*||t||^2.
__global__ void prep_kernel(const float* __restrict__ tgt) {
    int idx = blockIdx.x * blockDim.x + threadIdx.x;
    if (idx >= Bq * Mq) return;
    int b = idx / Mq, j = idx % Mq;
    float x = tgt[idx * 3 + 0];
    float y = tgt[idx * 3 + 1];
    float z = tgt[idx * 3 + 2];
    float* base = g_tsoa + b * 4 * Mq;
    base[0 * Mq + j] = x;
    base[1 * Mq + j] = y;
    base[2 * Mq + j] = z;
    base[3 * Mq + j] = 0.5f * (x * x + y * y + z * z);
}

// Kernel 2: main pairwise min. Each block: 1024 sources x 256 targets.
// d' = 0.5*||t||^2 - s.t  tracked packed (2 targets per fma.f32x2).
// Final ||s-t*||^2 = ||s||^2 + 2*min(d') recovered in the reduce kernel.
__global__ __launch_bounds__(THREADS) void nn_kernel(const float* __restrict__ src) {
    __shared__ __align__(16) float stx[CHUNK];
    __shared__ __align__(16) float sty[CHUNK];
    __shared__ __align__(16) float stz[CHUNK];
    __shared__ __align__(16) float sh2[CHUNK];

    const int tid = threadIdx.x;
    const int c = blockIdx.x;                       // target chunk
    const int sb = blockIdx.y;                      // source block
    const int b = sb / SRCBLK_PER_B;
    const int src0 = (sb % SRCBLK_PER_B) * SRC_PER_BLOCK;

    // Load this chunk's targets (SoA, coalesced, CHUNK == THREADS).
    const float* tb = g_tsoa + b * 4 * Mq;
    stx[tid] = tb[0 * Mq + c * CHUNK + tid];
    sty[tid] = tb[1 * Mq + c * CHUNK + tid];
    stz[tid] = tb[2 * Mq + c * CHUNK + tid];
    sh2[tid] = tb[3 * Mq + c * CHUNK + tid];
    __syncthreads();

    // Per-thread sources: negated + broadcast-packed once.
    unsigned long long nsx[S_PT], nsy[S_PT], nsz[S_PT];
#pragma unroll
    for (int s = 0; s < S_PT; s++) {
        int gi = b * Nq + src0 + s * THREADS + tid;
        float x = src[gi * 3 + 0];
        float y = src[gi * 3 + 1];
        float z = src[gi * 3 + 2];
        nsx[s] = pack2(-x, -x);
        nsy[s] = pack2(-y, -y);
        nsz[s] = pack2(-z, -z);
    }

    float m0[S_PT], m1[S_PT];
#pragma unroll
    for (int s = 0; s < S_PT; s++) {
        m0[s] = __int_as_float(0x7f800000);
        m1[s] = __int_as_float(0x7f800000);
    }

    const unsigned long long* px = (const unsigned long long*)stx;
    const unsigned long long* py = (const unsigned long long*)sty;
    const unsigned long long* pz = (const unsigned long long*)stz;
    const unsigned long long* ph = (const unsigned long long*)sh2;

#pragma unroll 4
    for (int jp = 0; jp < CHUNK / 2; jp++) {
        unsigned long long tx = px[jp];   // ld.shared.b64 (broadcast)
        unsigned long long ty = py[jp];
        unsigned long long tz = pz[jp];
        unsigned long long h  = ph[jp];
#pragma unroll
        for (int s = 0; s < S_PT; s++) {
            unsigned long long d = fma2(nsx[s], tx, h);
            d = fma2(nsy[s], ty, d);
            d = fma2(nsz[s], tz, d);
            m0[s] = fminf(m0[s], lo2(d));
            m1[s] = fminf(m1[s], hi2(d));
        }
    }

#pragma unroll
    for (int s = 0; s < S_PT; s++) {
        int gi = b * Nq + src0 + s * THREADS + tid;
        g_partial[c * BN + gi] = fminf(m0[s], m1[s]);   // coalesced store
    }
}

// Kernel 3: per-source min over chunks, add ||s||^2, block tree-sum (deterministic).
__global__ __launch_bounds__(THREADS) void reduce_kernel(const float* __restrict__ src) {
    __shared__ float red[THREADS];
    const int gi = blockIdx.x * THREADS + threadIdx.x;
    float mn = __int_as_float(0x7f800000);
#pragma unroll
    for (int cc = 0; cc < NCHUNK; cc++)
        mn = fminf(mn, g_partial[cc * BN + gi]);
    float x = src[gi * 3 + 0];
    float y = src[gi * 3 + 1];
    float z = src[gi * 3 + 2];
    float val = x * x + y * y + z * z + 2.0f * mn;      // ||s - t*||^2
    red[threadIdx.x] = val;
    __syncthreads();
    for (int o = THREADS / 2; o > 0; o >>= 1) {
        if (threadIdx.x < o) red[threadIdx.x] += red[threadIdx.x + o];
        __syncthreads();
    }
    if (threadIdx.x == 0) g_blocksum[blockIdx.x] = red[0];
}

// Kernel 4: final deterministic sum of 64 block sums -> mean loss.
__global__ void final_kernel(float* __restrict__ out) {
    __shared__ float red[NRBLK];
    int t = threadIdx.x;
    red[t] = g_blocksum[t];
    __syncthreads();
    for (int o = NRBLK / 2; o > 0; o >>= 1) {
        if (t < o) red[t] += red[t + o];
        __syncthreads();
    }
    if (t == 0) out[0] = red[0] * (1.0f / (float)(Bq * Nq * 3));
}

extern "C" void kernel_launch(void* const* d_in, const int* in_sizes, int n_in,
                              void* d_out, int out_size) {
    const float* src = (const float*)d_in[0];   // source_point_cloud [B,N,3]
    const float* tgt = (const float*)d_in[1];   // target_point_cloud [B,M,3]
    (void)in_sizes; (void)n_in; (void)out_size;

    prep_kernel<<<(Bq * Mq + THREADS - 1) / THREADS, THREADS>>>(tgt);
    nn_kernel<<<dim3(NCHUNK, NSRCBLK), THREADS>>>(src);
    reduce_kernel<<<NRBLK, THREADS>>>(src);
    final_kernel<<<1, NRBLK>>>((float*)d_out);
}

// round 2
// speedup vs baseline: 1.0559x; 1.0559x over previous
#include <cuda_runtime.h>

// Problem shape (fixed by the dataset): source [B,N,3], target [B,M,3], fp32.
#define Bq 2
#define Nq 8192
#define Mq 8192
#define THREADS 256
#define S_PT 4                                  // sources per thread (register blocked)
#define SRC_PER_BLOCK (THREADS * S_PT)          // 1024
#define NCHUNK 32                               // target chunks -> grid parallelism
#define CHUNK (Mq / NCHUNK)                     // 256 targets per chunk (== THREADS)
#define SRCBLK_PER_B (Nq / SRC_PER_BLOCK)       // 8
#define NSRCBLK (Bq * SRCBLK_PER_B)             // 16
#define BN (Bq * Nq)                            // 16384 sources total
#define NRBLK (BN / THREADS)                    // 64 reduce blocks

// Scratch (no allocations allowed).
__device__ float g_partial[NCHUNK * BN];        // [chunk][global source] partial mins
__device__ float g_blocksum[NRBLK];
__device__ int   g_ticket;                      // zero-init; self-resets each run

// ---- packed f32x2 helpers (sm_100+; ptxas will not auto-fuse, must be PTX) ----
__device__ __forceinline__ unsigned long long pack2(float a, float b) {
    unsigned long long r;
    asm("mov.b64 %0, {%1, %2};" : "=l"(r) : "f"(a), "f"(b));
    return r;
}
__device__ __forceinline__ unsigned long long fma2(unsigned long long a,
                                                   unsigned long long b,
                                                   unsigned long long c) {
    unsigned long long d;
    asm("fma.rn.f32x2 %0, %1, %2, %3;" : "=l"(d) : "l"(a), "l"(b), "l"(c));
    return d;
}
__device__ __forceinline__ float lo2(unsigned long long v) {
    return __uint_as_float((unsigned int)v);
}
__device__ __forceinline__ float hi2(unsigned long long v) {
    return __uint_as_float((unsigned int)(v >> 32));
}

// Kernel 1: main pairwise min. Each block: 1024 sources x 256 targets.
// Builds its target SoA chunk (+ ht2 = 0.5*||t||^2) in smem from AoS global.
// d' = 0.5*||t||^2 - s.t  tracked packed (2 targets per fma.rn.f32x2).
// Final ||s-t*||^2 = ||s||^2 + 2*min(d') recovered in the reduce kernel.
__global__ __launch_bounds__(THREADS) void nn_kernel(
    const float* __restrict__ src, const float* __restrict__ tgt) {
    __shared__ __align__(16) float stx[CHUNK];
    __shared__ __align__(16) float sty[CHUNK];
    __shared__ __align__(16) float stz[CHUNK];
    __shared__ __align__(16) float sh2[CHUNK];

    const int tid = threadIdx.x;
    const int c = blockIdx.x;                       // target chunk
    const int sb = blockIdx.y;                      // source block
    const int b = sb / SRCBLK_PER_B;
    const int src0 = (sb % SRCBLK_PER_B) * SRC_PER_BLOCK;

    // Load this chunk's targets: coalesced AoS read, scatter to SoA smem.
    const float* tbase = tgt + (b * Mq + c * CHUNK) * 3;
#pragma unroll
    for (int i = tid; i < CHUNK * 3; i += THREADS) {
        float v = tbase[i];
        int j = i / 3, d = i % 3;
        (d == 0 ? stx : (d == 1 ? sty : stz))[j] = v;
    }
    __syncthreads();
    {
        float x = stx[tid], y = sty[tid], z = stz[tid];
        sh2[tid] = 0.5f * (x * x + y * y + z * z);
    }
    __syncthreads();

    // Per-thread sources: negated + broadcast-packed once.
    unsigned long long nsx[S_PT], nsy[S_PT], nsz[S_PT];
#pragma unroll
    for (int s = 0; s < S_PT; s++) {
        int gi = b * Nq + src0 + s * THREADS + tid;
        float x = src[gi * 3 + 0];
        float y = src[gi * 3 + 1];
        float z = src[gi * 3 + 2];
        nsx[s] = pack2(-x, -x);
        nsy[s] = pack2(-y, -y);
        nsz[s] = pack2(-z, -z);
    }

    float m0[S_PT], m1[S_PT];
#pragma unroll
    for (int s = 0; s < S_PT; s++) {
        m0[s] = __int_as_float(0x7f800000);
        m1[s] = __int_as_float(0x7f800000);
    }

    const unsigned long long* px = (const unsigned long long*)stx;
    const unsigned long long* py = (const unsigned long long*)sty;
    const unsigned long long* pz = (const unsigned long long*)stz;
    const unsigned long long* ph = (const unsigned long long*)sh2;

#pragma unroll 4
    for (int jp = 0; jp < CHUNK / 2; jp++) {
        unsigned long long tx = px[jp];   // ld.shared.b64 (broadcast)
        unsigned long long ty = py[jp];
        unsigned long long tz = pz[jp];
        unsigned long long h  = ph[jp];
#pragma unroll
        for (int s = 0; s < S_PT; s++) {
            unsigned long long d = fma2(nsx[s], tx, h);
            d = fma2(nsy[s], ty, d);
            d = fma2(nsz[s], tz, d);
            m0[s] = fminf(m0[s], lo2(d));
            m1[s] = fminf(m1[s], hi2(d));
        }
    }

#pragma unroll
    for (int s = 0; s < S_PT; s++) {
        int gi = b * Nq + src0 + s * THREADS + tid;
        g_partial[c * BN + gi] = fminf(m0[s], m1[s]);   // coalesced store
    }
}

// Kernel 2: per-source min over chunks, add ||s||^2, block tree-sum, then the
// LAST block (threadfence-reduction ticket) sums the 64 block sums in a fixed
// tree order -> deterministic final mean. Ticket self-resets for graph replay.
__global__ __launch_bounds__(THREADS) void reduce_kernel(
    const float* __restrict__ src, float* __restrict__ out) {
    __shared__ float red[THREADS];
    __shared__ bool is_last;
    const int gi = blockIdx.x * THREADS + threadIdx.x;
    float mn = __int_as_float(0x7f800000);
#pragma unroll
    for (int cc = 0; cc < NCHUNK; cc++)
        mn = fminf(mn, g_partial[cc * BN + gi]);
    float x = src[gi * 3 + 0];
    float y = src[gi * 3 + 1];
    float z = src[gi * 3 + 2];
    float val = x * x + y * y + z * z + 2.0f * mn;      // ||s - t*||^2
    red[threadIdx.x] = val;
    __syncthreads();
#pragma unroll
    for (int o = THREADS / 2; o > 0; o >>= 1) {
        if (threadIdx.x < o) red[threadIdx.x] += red[threadIdx.x + o];
        __syncthreads();
    }
    if (threadIdx.x == 0) {
        g_blocksum[blockIdx.x] = red[0];
        __threadfence();
        int t = atomicAdd(&g_ticket, 1);
        is_last = (t == NRBLK - 1);
    }
    __syncthreads();
    if (is_last) {
        __threadfence();
        if (threadIdx.x < NRBLK) red[threadIdx.x] = g_blocksum[threadIdx.x];
        __syncthreads();
#pragma unroll
        for (int o = NRBLK / 2; o > 0; o >>= 1) {
            if (threadIdx.x < o) red[threadIdx.x] += red[threadIdx.x + o];
            __syncthreads();
        }
        if (threadIdx.x == 0) {
            out[0] = red[0] * (1.0f / (float)(Bq * Nq * 3));
            g_ticket = 0;                                // reset for next replay
        }
    }
}

extern "C" void kernel_launch(void* const* d_in, const int* in_sizes, int n_in,
                              void* d_out, int out_size) {
    const float* src = (const float*)d_in[0];   // source_point_cloud [B,N,3]
    const float* tgt = (const float*)d_in[1];   // target_point_cloud [B,M,3]
    (void)in_sizes; (void)n_in; (void)out_size;

    nn_kernel<<<dim3(NCHUNK, NSRCBLK), THREADS>>>(src, tgt);
    reduce_kernel<<<NRBLK, THREADS>>>(src, (float*)d_out);
}